// round 3
// baseline (speedup 1.0000x reference)
#include <cuda_runtime.h>
#include <math.h>

#define TDIM 600
#define BATCH 32
#define NBUF (BATCH*128*TDIM)

__device__ __align__(1024) float g_sp[NBUF];
__device__ __align__(1024) float g_o1[NBUF];
__device__ __align__(1024) float g_o2[NBUF];
__device__ __align__(1024) float g_o3[NBUF];
__device__ __align__(1024) float g_bA[NBUF];
__device__ __align__(1024) float g_bB[NBUF];
__device__ float g_se[BATCH*128];
__device__ float g_pool[BATCH*1024];

// out[b,o,t] = bn(relu(sum_c W[o,c]*in[b,c,t] + bias[o]))
// input row k: (k>=kTail? tail : inA (+inB))
__global__ __launch_bounds__(256) void k_gemm(
    const float* __restrict__ W, const float* __restrict__ bias,
    const float* __restrict__ bn,
    const float* __restrict__ inA, long long aStr,
    const float* __restrict__ inB, long long bStr,
    const float* __restrict__ tail, int kTail,
    float* __restrict__ out)
{
    __shared__ float Ws[32][132];
    __shared__ float Bs[32][68];
    __shared__ float sA[128], sBb[128], sBi[128];
    const int b = blockIdx.y, t0 = blockIdx.x*64, tid = threadIdx.x;

    if (tid < 128) {
        float g=bn[tid], be=bn[128+tid], mm=bn[256+tid], vv=bn[384+tid];
        float a = g*rsqrtf(vv+1e-5f);
        sA[tid]=a; sBb[tid]=be-mm*a; sBi[tid]=bias[tid];
    }
    const float* pA = inA + (long long)b*aStr;
    const float* pB = inB ? inB + (long long)b*bStr : nullptr;
    const float* pT = tail ? tail + (long long)b*(128*TDIM) : nullptr;

    float acc[8][4];
    #pragma unroll
    for (int r=0;r<8;++r){ acc[r][0]=acc[r][1]=acc[r][2]=acc[r][3]=0.f; }
    const int tx = tid&15, ty = tid>>4;
    const int cBase = tx*4, rBase = ty*8;

    for (int k0=0;k0<128;k0+=32){
        __syncthreads();
        #pragma unroll
        for (int it=0;it<4;++it){
            int idx=it*256+tid, mo=idx>>3, kg=(idx&7)<<2;
            float4 w4 = *reinterpret_cast<const float4*>(W + mo*128 + k0 + kg);
            Ws[kg+0][mo]=w4.x; Ws[kg+1][mo]=w4.y; Ws[kg+2][mo]=w4.z; Ws[kg+3][mo]=w4.w;
        }
        #pragma unroll
        for (int it=0;it<2;++it){
            int idx=it*256+tid, kk=idx>>4, cg=(idx&15)<<2;
            int k=k0+kk, t=t0+cg;
            const float* src = (k>=kTail)? (pT + k*TDIM) : (pA + (long long)k*TDIM);
            bool addB = pB && (k<kTail);
            float4 v4;
            if (t+3 < TDIM){
                v4 = *reinterpret_cast<const float4*>(src + t);
                if (addB){
                    float4 u = *reinterpret_cast<const float4*>(pB + (long long)k*TDIM + t);
                    v4.x+=u.x; v4.y+=u.y; v4.z+=u.z; v4.w+=u.w;
                }
            } else {
                float tmp[4];
                #pragma unroll
                for (int q=0;q<4;++q){
                    int tt=t+q; float xv=0.f;
                    if (tt<TDIM){ xv=src[tt]; if(addB) xv+=pB[(long long)k*TDIM+tt]; }
                    tmp[q]=xv;
                }
                v4 = make_float4(tmp[0],tmp[1],tmp[2],tmp[3]);
            }
            *reinterpret_cast<float4*>(&Bs[kk][cg]) = v4;
        }
        __syncthreads();
        #pragma unroll
        for (int kk=0;kk<32;++kk){
            float4 a0=*reinterpret_cast<const float4*>(&Ws[kk][rBase]);
            float4 a1=*reinterpret_cast<const float4*>(&Ws[kk][rBase+4]);
            float4 bv=*reinterpret_cast<const float4*>(&Bs[kk][cBase]);
            float av[8]={a0.x,a0.y,a0.z,a0.w,a1.x,a1.y,a1.z,a1.w};
            float bb[4]={bv.x,bv.y,bv.z,bv.w};
            #pragma unroll
            for (int r=0;r<8;++r)
                #pragma unroll
                for (int q=0;q<4;++q)
                    acc[r][q]=fmaf(av[r],bb[q],acc[r][q]);
        }
    }
    if (t0+cBase+3 < TDIM){
        float* po = out + ((long long)b*128 + rBase)*TDIM + t0 + cBase;
        #pragma unroll
        for (int r=0;r<8;++r){
            int o=rBase+r; float a=sA[o], c2=sBb[o], bi=sBi[o];
            float4 v4;
            v4.x=fmaxf(acc[r][0]+bi,0.f)*a+c2;
            v4.y=fmaxf(acc[r][1]+bi,0.f)*a+c2;
            v4.z=fmaxf(acc[r][2]+bi,0.f)*a+c2;
            v4.w=fmaxf(acc[r][3]+bi,0.f)*a+c2;
            *reinterpret_cast<float4*>(po + r*TDIM) = v4;
        }
    }
}

// inner dilated conv step j: S=j+2 scale planes
__global__ __launch_bounds__(256) void k_iconv(
    int j, const float* __restrict__ o1,
    const float* __restrict__ bufPrev, float* __restrict__ bufOut,
    const float* __restrict__ cwj, const float* __restrict__ cbj,
    const float* __restrict__ ibnj, const float* __restrict__ wsj,
    float* __restrict__ o2)
{
    __shared__ float sm[16][132];
    const int b=blockIdx.y, t0=blockIdx.x*128;
    const int lane=threadIdx.x, o=lane&15, par=lane>>4;
    const int t2b=threadIdx.y*8, tid=threadIdx.y*32+lane;
    const int ub = 2*t2b+par;

    float rw[48];
    #pragma unroll
    for (int q=0;q<48;++q) rw[q]=__ldg(cwj + o*48 + q);
    const float cb0=__ldg(cbj+o);
    float g=ibnj[o], be=ibnj[16+o], mm=ibnj[32+o], vv=ibnj[48+o];
    float bnA=g*rsqrtf(vv+1e-5f), bnB=be-mm*bnA;

    const int S=j+2;
    float bsum[8];
    #pragma unroll
    for (int x=0;x<8;++x) bsum[x]=0.f;

    for (int s=0;s<S;++s){
        const float* src;
        if (j==0)      src = o1 + ((long long)b*128 + (s==0?112:0))*TDIM;
        else if (s<=j) src = bufPrev + ((long long)(s*BATCH+b)*16)*TDIM;
        else           src = o1 + ((long long)b*128 + j*16)*TDIM;
        __syncthreads();
        for (int idx=tid; idx<16*132; idx+=256){
            int ii=idx/132, w=idx-ii*132, t=t0-2+w;
            sm[ii][w] = (t>=0 && t<TDIM) ? src[ii*TDIM+t] : 0.f;
        }
        __syncthreads();
        float acc[8];
        #pragma unroll
        for (int x=0;x<8;++x) acc[x]=cb0;
        #pragma unroll
        for (int i=0;i<16;++i){
            float v[10];
            #pragma unroll
            for (int m=0;m<10;++m) v[m]=sm[i][ub+2*m];
            #pragma unroll
            for (int k=0;k<3;++k){
                float wv=rw[i*3+k];
                #pragma unroll
                for (int x=0;x<8;++x) acc[x]=fmaf(wv,v[x+k],acc[x]);
            }
        }
        float wss=wsj[s];
        float* dst = bufOut + ((long long)(s*BATCH+b)*16 + o)*TDIM;
        #pragma unroll
        for (int x=0;x<8;++x){
            int t=t0+2*(t2b+x)+par;
            float spv=fmaxf(acc[x],0.f)*bnA+bnB;
            if (t<TDIM) dst[t]=spv;
            bsum[x]+=spv*wss;
        }
    }
    float* d2 = o2 + ((long long)b*128 + j*16 + o)*TDIM;
    #pragma unroll
    for (int x=0;x<8;++x){
        int t=t0+2*(t2b+x)+par;
        if (t<TDIM) d2[t]=bsum[x];
    }
}

__global__ __launch_bounds__(256) void k_se(
    const float* __restrict__ o3,
    const float* __restrict__ s1w, const float* __restrict__ s1b,
    const float* __restrict__ s2w, const float* __restrict__ s2b,
    float* __restrict__ seo)
{
    const int b=blockIdx.x, tid=threadIdx.x, w=tid>>5, lane=tid&31;
    __shared__ float m[128], s1[16];
    for (int c=w;c<128;c+=8){
        const float* p = o3 + ((long long)b*128+c)*TDIM;
        float s=0.f;
        for (int t=lane;t<TDIM;t+=32) s+=p[t];
        #pragma unroll
        for (int off=16;off;off>>=1) s+=__shfl_down_sync(0xffffffffu,s,off);
        if (!lane) m[c]=s*(1.f/600.f);
    }
    __syncthreads();
    if (tid<16){
        float s=s1b[tid];
        for (int c=0;c<128;++c) s=fmaf(s1w[tid*128+c],m[c],s);
        s1[tid]=fmaxf(s,0.f);
    }
    __syncthreads();
    if (tid<128){
        float s=s2b[tid];
        #pragma unroll
        for (int oo=0;oo<16;++oo) s=fmaf(s2w[tid*16+oo],s1[oo],s);
        seo[b*128+tid]=1.f/(1.f+expf(-s));
    }
}

__global__ __launch_bounds__(128) void k_apply(
    const float* __restrict__ o3, const float* __restrict__ se,
    const float* __restrict__ xi, const float* spPrev,
    const float* __restrict__ obn, const float* __restrict__ fbn, int gcBase,
    float* spOut, float* __restrict__ pooled)
{
    const int c=blockIdx.x, b=blockIdx.y, tid=threadIdx.x;
    const int gc=gcBase+c;
    float oA=obn[c]*rsqrtf(obn[384+c]+1e-5f);
    float oB=obn[128+c]-obn[256+c]*oA;
    float fA=fbn[gc]*rsqrtf(fbn[3072+gc]+1e-5f);
    float fB=fbn[1024+gc]-fbn[2048+gc]*fA;
    float sc=se[b*128+c];
    const float* p3 = o3 + ((long long)b*128+c)*TDIM;
    const float* px = xi + (long long)b*1024*TDIM + (long long)c*TDIM;
    const float* pp = spPrev ? spPrev + ((long long)b*128+c)*TDIM : nullptr;
    float* po = spOut + ((long long)b*128+c)*TDIM;
    float s=0.f;
    for (int t=tid;t<TDIM;t+=128){
        float r = px[t] + (pp ? pp[t] : 0.f);
        float v = p3[t]*sc + r;
        float sp = fmaxf(v,0.f)*oA + oB;
        po[t]=sp;
        s += fmaxf(sp*fA+fB, 0.f);
    }
    __shared__ float red[128];
    red[tid]=s; __syncthreads();
    for (int o=64;o;o>>=1){ if(tid<o) red[tid]+=red[tid+o]; __syncthreads(); }
    if (!tid) pooled[b*1024+gc]=red[0]*(1.f/600.f);
}

__global__ __launch_bounds__(128) void k_ptail(
    const float* __restrict__ x, const float* __restrict__ fbn,
    float* __restrict__ pooled)
{
    const int c=blockIdx.x, b=blockIdx.y, tid=threadIdx.x;
    const int gc=896+c;
    float fA=fbn[gc]*rsqrtf(fbn[3072+gc]+1e-5f);
    float fB=fbn[1024+gc]-fbn[2048+gc]*fA;
    const float* px = x + ((long long)b*1024+gc)*TDIM;
    float s=0.f;
    for (int t=tid;t<TDIM;t+=128) s+=fmaxf(px[t]*fA+fB,0.f);
    __shared__ float red[128];
    red[tid]=s; __syncthreads();
    for (int o=64;o;o>>=1){ if(tid<o) red[tid]+=red[tid+o]; __syncthreads(); }
    if (!tid) pooled[b*1024+gc]=red[0]*(1.f/600.f);
}

__global__ __launch_bounds__(256) void k_fc(
    const float* __restrict__ pooled, const float* __restrict__ fcw,
    const float* __restrict__ fcb, float* __restrict__ out)
{
    const int b=blockIdx.x, tid=threadIdx.x;
    float s0=0.f, s1=0.f;
    for (int c=tid;c<1024;c+=256){
        float p=pooled[b*1024+c];
        s0=fmaf(p,fcw[c],s0);
        s1=fmaf(p,fcw[1024+c],s1);
    }
    __shared__ float r0[256], r1[256];
    r0[tid]=s0; r1[tid]=s1; __syncthreads();
    for (int o=128;o;o>>=1){ if(tid<o){r0[tid]+=r0[tid+o]; r1[tid]+=r1[tid+o];} __syncthreads(); }
    if (!tid){ out[b*2]=r0[0]+fcb[0]; out[b*2+1]=r1[0]+fcb[1]; }
}

extern "C" void kernel_launch(void* const* d_in, const int* in_sizes, int n_in,
                              void* d_out, int out_size)
{
    // roles: 0:x 1:w1 2:b1 3:bn1 4:cw 5:cb 6:ibn 7..13:ws0..6
    //        14:w3 15:b3 16:bn3 17:se1w 18:se1b 19:se2w 20:se2b 21:obn 22:fbn 23:fcw 24:fcb
    const float* P[25] = {nullptr};
    int n896=0, n3584=0, n114688=0, n14336=0;
    for (int i=0;i<n_in;++i){
        int s=in_sizes[i]; const float* p=(const float*)d_in[i];
        switch(s){
            case 19660800: P[0]=p; break;
            case 114688: P[n114688++?14:1]=p; break;
            case 896: P[n896==0?2:(n896==1?15:20)]=p; n896++; break;
            case 3584: P[n3584==0?3:(n3584==1?16:21)]=p; n3584++; break;
            case 37632: P[4]=p; break;
            case 784: P[5]=p; break;
            case 3136: P[6]=p; break;
            case 14: P[7]=p; break;  case 21: P[8]=p; break;
            case 28: P[9]=p; break;  case 35: P[10]=p; break;
            case 42: P[11]=p; break; case 49: P[12]=p; break;
            case 56: P[13]=p; break;
            case 14336: P[n14336++?19:17]=p; break;
            case 112: P[18]=p; break;
            case 4096: P[22]=p; break;
            case 2048: P[23]=p; break;
            case 2: P[24]=p; break;
            default: break;
        }
    }
    float *sp,*o1,*o2,*o3,*bA,*bB,*se,*pool;
    cudaGetSymbolAddress((void**)&sp, g_sp);
    cudaGetSymbolAddress((void**)&o1, g_o1);
    cudaGetSymbolAddress((void**)&o2, g_o2);
    cudaGetSymbolAddress((void**)&o3, g_o3);
    cudaGetSymbolAddress((void**)&bA, g_bA);
    cudaGetSymbolAddress((void**)&bB, g_bB);
    cudaGetSymbolAddress((void**)&se, g_se);
    cudaGetSymbolAddress((void**)&pool, g_pool);
    float* out = (float*)d_out;

    dim3 gG(10,32);
    dim3 gI(5,32), bI(32,8);
    for (int i=0;i<7;++i){
        const float* xi = P[0] + (long long)i*128*TDIM;
        k_gemm<<<gG,256>>>(P[1]+i*16384, P[2]+i*128, P[3]+i*512,
                           xi, 1024LL*TDIM, i? sp:nullptr, 128LL*TDIM,
                           nullptr, 128, o1);
        float* bufs[2] = {bA,bB};
        for (int j=0;j<7;++j){
            k_iconv<<<gI,bI>>>(j, o1, bufs[(j+1)&1], bufs[j&1],
                               P[4]+(i*7+j)*768, P[5]+(i*7+j)*16,
                               P[6]+(i*7+j)*64, P[7+j]+i*(j+2), o2);
        }
        k_gemm<<<gG,256>>>(P[14]+i*16384, P[15]+i*128, P[16]+i*512,
                           o2, 128LL*TDIM, nullptr, 0,
                           o1, 112, o3);
        k_se<<<32,256>>>(o3, P[17]+i*2048, P[18]+i*16, P[19]+i*2048, P[20]+i*128, se);
        k_apply<<<dim3(128,32),128>>>(o3, se, xi, i? sp:nullptr,
                                      P[21]+i*512, P[22], i*128, sp, pool);
    }
    k_ptail<<<dim3(128,32),128>>>(P[0], P[22], pool);
    k_fc<<<32,256>>>(pool, P[23], P[24], out);
}